// round 9
// baseline (speedup 1.0000x reference)
#include <cuda_runtime.h>
#include <cuda_fp16.h>
#include <cstdint>

// ---------------- problem caps ----------------
#define NMAX 50048
#define EMAX 800000
#define ETMAX (EMAX + NMAX)
#define SCAN_B 256
#define SCAN_G ((NMAX + SCAN_B - 1) / SCAN_B)

// ---------------- scratch (device globals; no runtime alloc) ----------------
__device__ __half g_xh[NMAX * 64];      // x in fp16 (6.4 MB, L2-resident gather table)
__device__ __half g_A[NMAX * 256];      // per-head aggregated x, head-stacked, fp16
__device__ __half g_bmat[64 * 256];     // rearranged W: bmat[j][h*64+kk] = W[kk][h*64+j]
__device__ float  g_asrc[NMAX * 4];
__device__ float  g_adst[NMAX * 4];
__device__ int    g_count[NMAX];        // zeroed invariant (scan re-zeroes after use)
__device__ int    g_offset[NMAX + 1];
__device__ int    g_cursor[NMAX];
__device__ int2   g_pay[ETMAX];         // {src, eav} per CSR slot
__device__ unsigned long long g_scanpkt[SCAN_G];   // lookback {state,value}; reset by k_main
__device__ float  g_mean_partial[512];
__device__ float  g_shead[4];
__device__ float  g_meanv;

// ---------------- kernels ----------------

// Fused: x->fp16, W rearrange, mean partials, degree atomics, a_src/a_dst,
// shead, scan-packet reset. va computed block-locally in smem.
__global__ void k_main(const float* __restrict__ x, const float* __restrict__ ea,
                       const float* __restrict__ W, const float* __restrict__ att_src,
                       const float* __restrict__ att_dst, const float* __restrict__ lew,
                       const float* __restrict__ ae, const int* __restrict__ dstidx,
                       int n, int E) {
    __shared__ float sva[512];
    int t = threadIdx.x;
    // local va: thread t -> (h = t>>6, k = t&63) dots of length 64
    {
        int h = t >> 6, k = t & 63;
        const float* wrow = &W[k * 256 + h * 64];
        const float* as = &att_src[h * 64];
        const float* ad = &att_dst[h * 64];
        float vs = 0.0f, vd = 0.0f;
        #pragma unroll 8
        for (int c = 0; c < 64; c++) { float wv = wrow[c]; vs += wv * as[c]; vd += wv * ad[c]; }
        sva[t] = vs;
        sva[256 + t] = vd;
    }
    if (blockIdx.x == 0) {
        if (t < 4) {
            float p = 0.0f;
            for (int c = 0; c < 64; c++) p += lew[t * 64 + c] * ae[t * 64 + c];
            g_shead[t] = p;
        }
        if (t < SCAN_G) g_scanpkt[t] = 0ULL;       // reset lookback state each replay
    }
    __syncthreads();

    int tid = blockIdx.x * blockDim.x + t;
    int stride = gridDim.x * blockDim.x;

    // x -> fp16 gather table
    int nh2 = n * 32;
    for (int i = tid; i < nh2; i += stride) {
        float2 v = ((const float2*)x)[i];
        ((half2*)g_xh)[i] = __floats2half2_rn(v.x, v.y);
    }
    // W rearrange for out-gemm
    for (int idx = tid; idx < 64 * 256; idx += stride) {
        int j = idx >> 8, k = idx & 255;
        int h = k >> 6, kk = k & 63;
        g_bmat[idx] = __float2half(W[kk * 256 + h * 64 + j]);
    }
    // degree counting (counts EXCLUDE self-loops; array starts zeroed)
    for (int e = tid; e < E; e += stride) atomicAdd(&g_count[dstidx[e]], 1);

    // edge_attr mean partial
    float s = 0.0f;
    for (int i = tid; i < E; i += stride) s += ea[i];
    #pragma unroll
    for (int o = 16; o; o >>= 1) s += __shfl_xor_sync(0xffffffffu, s, o);
    __shared__ float sm[8];
    if ((t & 31) == 0) sm[t >> 5] = s;
    __syncthreads();
    if (t == 0) {
        float v = 0.0f;
        #pragma unroll
        for (int j = 0; j < 8; j++) v += sm[j];
        g_mean_partial[blockIdx.x] = v;
    }

    // per-node a_src/a_dst (warp per node, fp32 x)
    int lane = t & 31;
    int warp = tid >> 5;
    int nwarp = stride >> 5;
    for (int node = warp; node < n; node += nwarp) {
        float2 xv = ((const float2*)x)[node * 32 + lane];
        float p[8];
        #pragma unroll
        for (int h = 0; h < 4; h++) {
            p[h]     = xv.x * sva[h * 64 + 2 * lane]       + xv.y * sva[h * 64 + 2 * lane + 1];
            p[4 + h] = xv.x * sva[256 + h * 64 + 2 * lane] + xv.y * sva[256 + h * 64 + 2 * lane + 1];
        }
        #pragma unroll
        for (int o = 16; o; o >>= 1) {
            #pragma unroll
            for (int j = 0; j < 8; j++) p[j] += __shfl_xor_sync(0xffffffffu, p[j], o);
        }
        if (lane == 0) {
            *(float4*)&g_asrc[node * 4] = make_float4(p[0], p[1], p[2], p[3]);
            *(float4*)&g_adst[node * 4] = make_float4(p[4], p[5], p[6], p[7]);
        }
    }
}

// Single-pass decoupled-lookback exclusive scan of (count+1) -> offset/cursor.
// Re-zeroes count. Block 0 also reduces meanv. offset[n] written by last block.
__global__ void k_scan(int n, int nb, int E) {
    __shared__ int ss[SCAN_B];
    __shared__ int sbase;
    int t = threadIdx.x, bid = blockIdx.x;
    int i = bid * SCAN_B + t;
    int v = (i < n) ? g_count[i] + 1 : 0;     // +1 = self-loop
    ss[t] = v;
    __syncthreads();
    #pragma unroll
    for (int o = 1; o < SCAN_B; o <<= 1) {
        int u = (t >= o) ? ss[t - o] : 0;
        __syncthreads();
        ss[t] += u;
        __syncthreads();
    }
    int total = ss[SCAN_B - 1];

    if (t == 0) {
        if (bid == 0) {
            *(volatile unsigned long long*)&g_scanpkt[0] =
                (2ULL << 32) | (unsigned long long)(unsigned)total;
            sbase = 0;
        } else {
            *(volatile unsigned long long*)&g_scanpkt[bid] =
                (1ULL << 32) | (unsigned long long)(unsigned)total;
            int run = 0;
            int j = bid - 1;
            while (true) {
                unsigned long long p;
                do { p = *(volatile unsigned long long*)&g_scanpkt[j]; } while ((p >> 32) == 0ULL);
                run += (int)(unsigned)p;
                if ((p >> 32) == 2ULL) break;
                j--;
            }
            *(volatile unsigned long long*)&g_scanpkt[bid] =
                (2ULL << 32) | (unsigned long long)(unsigned)(run + total);
            sbase = run;
        }
    }
    __syncthreads();
    int base = sbase;
    if (i < n) {
        int off = base + ss[t] - v;
        g_offset[i] = off;
        g_cursor[i] = off;
        g_count[i] = 0;                        // maintain zeroed invariant
    }
    if (bid == nb - 1 && t == SCAN_B - 1) g_offset[n] = base + total;

    // block 0: meanv from main's partials
    if (bid == 0) {
        float m = g_mean_partial[t] + g_mean_partial[t + 256];
        #pragma unroll
        for (int o = 16; o; o >>= 1) m += __shfl_xor_sync(0xffffffffu, m, o);
        __shared__ float smf[8];
        if ((t & 31) == 0) smf[t >> 5] = m;
        __syncthreads();
        if (t == 0) {
            float s = 0.0f;
            #pragma unroll
            for (int j = 0; j < 8; j++) s += smf[j];
            g_meanv = s / (float)E;
        }
    }
}

// scatter: build fat CSR payload {src, eav} (sequential reads, one random 8B store)
__global__ void k_scatter(const int* __restrict__ srcidx, const int* __restrict__ dstidx,
                          const float* __restrict__ ea, int E, int n) {
    int e = blockIdx.x * blockDim.x + threadIdx.x;
    if (e >= E + n) return;
    int d, src; float eav;
    if (e < E) { d = dstidx[e]; src = srcidx[e]; eav = ea[e]; }
    else       { d = e - E;     src = e - E;     eav = g_meanv; }
    int pos = atomicAdd(&g_cursor[d], 1);
    g_pay[pos] = make_int2(src, __float_as_int(eav));
}

// warp per destination node: aggregate softmax-weighted x (fp16, 64 ch) per head.
__global__ void k_agg(int n) {
    int gw = (blockIdx.x * blockDim.x + threadIdx.x) >> 5;
    int lane = threadIdx.x & 31;
    if (gw >= n) return;

    float sh0 = g_shead[0], sh1 = g_shead[1], sh2 = g_shead[2], sh3 = g_shead[3];
    float4 adv = *(const float4*)&g_adst[gw * 4];

    int start = g_offset[gw];
    int end = g_offset[gw + 1];

    float a00 = 0.f, a01 = 0.f, a10 = 0.f, a11 = 0.f;
    float a20 = 0.f, a21 = 0.f, a30 = 0.f, a31 = 0.f;
    float ws0 = 0.f, ws1 = 0.f, ws2 = 0.f, ws3 = 0.f;
    const half2* xh2 = (const half2*)g_xh;

    for (int base = start; base < end; base += 32) {
        int i = base + lane;
        float w0 = 0.f, w1 = 0.f, w2 = 0.f, w3 = 0.f;
        int src = 0;
        if (i < end) {
            int2 pv = g_pay[i];
            src = pv.x;
            float eav = __int_as_float(pv.y);
            float4 as = *(const float4*)&g_asrc[src * 4];
            float l0 = as.x + adv.x + eav * sh0; l0 = (l0 > 0.f) ? l0 : 0.2f * l0;
            float l1 = as.y + adv.y + eav * sh1; l1 = (l1 > 0.f) ? l1 : 0.2f * l1;
            float l2 = as.z + adv.z + eav * sh2; l2 = (l2 > 0.f) ? l2 : 0.2f * l2;
            float l3 = as.w + adv.w + eav * sh3; l3 = (l3 > 0.f) ? l3 : 0.2f * l3;
            w0 = __expf(l0); w1 = __expf(l1); w2 = __expf(l2); w3 = __expf(l3);
        }
        int cnt = min(32, end - base);
        for (int j = 0; j < cnt; j++) {
            int   s  = __shfl_sync(0xffffffffu, src, j);
            float wa = __shfl_sync(0xffffffffu, w0,  j);
            float wb = __shfl_sync(0xffffffffu, w1,  j);
            float wc = __shfl_sync(0xffffffffu, w2,  j);
            float wd = __shfl_sync(0xffffffffu, w3,  j);
            float2 f = __half22float2(xh2[(size_t)s * 32 + lane]);
            a00 += wa * f.x; a01 += wa * f.y; ws0 += wa;
            a10 += wb * f.x; a11 += wb * f.y; ws1 += wb;
            a20 += wc * f.x; a21 += wc * f.y; ws2 += wc;
            a30 += wd * f.x; a31 += wd * f.y; ws3 += wd;
        }
    }

    float i0 = 0.25f / (ws0 + 1e-16f);   // fold 1/4 head-mean into normalize
    float i1 = 0.25f / (ws1 + 1e-16f);
    float i2 = 0.25f / (ws2 + 1e-16f);
    float i3 = 0.25f / (ws3 + 1e-16f);

    half2* A2 = (half2*)g_A + (size_t)gw * 128 + lane;
    A2[0]  = __floats2half2_rn(a00 * i0, a01 * i0);
    A2[32] = __floats2half2_rn(a10 * i1, a11 * i1);
    A2[64] = __floats2half2_rn(a20 * i2, a21 * i2);
    A2[96] = __floats2half2_rn(a30 * i3, a31 * i3);
}

__device__ __forceinline__ void mma16816(float* c, uint32_t a0, uint32_t a1,
                                         uint32_t a2, uint32_t a3,
                                         uint32_t b0, uint32_t b1) {
    asm("mma.sync.aligned.m16n8k16.row.col.f32.f16.f16.f32 "
        "{%0,%1,%2,%3}, {%4,%5,%6,%7}, {%8,%9}, {%0,%1,%2,%3};"
        : "+f"(c[0]), "+f"(c[1]), "+f"(c[2]), "+f"(c[3])
        : "r"(a0), "r"(a1), "r"(a2), "r"(a3), "r"(b0), "r"(b1));
}

// out = relu( A @ bmat + bias ) + x.
__global__ void k_outgemm(const float* __restrict__ x, const float* __restrict__ bias,
                          float* __restrict__ out, int n) {
    __shared__ __half As[64 * 136];
    __shared__ __half Bs[64 * 136];
    int tid = threadIdx.x;
    int base = blockIdx.x * 64;
    int w = tid >> 5, lane = tid & 31;
    int gid = lane >> 2, tig = lane & 3;
    int r0 = (w & 3) * 16, c0 = (w >> 2) * 32;

    float acc[4][4];
    #pragma unroll
    for (int nt = 0; nt < 4; nt++)
        #pragma unroll
        for (int j = 0; j < 4; j++) acc[nt][j] = 0.0f;

    #pragma unroll
    for (int kh = 0; kh < 2; kh++) {
        for (int i = tid; i < 1024; i += 256) {
            int r = i >> 4, cc = i & 15;
            int node = base + r;
            uint4 v = (node < n) ? *(const uint4*)&g_A[(size_t)node * 256 + kh * 128 + cc * 8]
                                 : make_uint4(0u, 0u, 0u, 0u);
            *(uint4*)&As[r * 136 + cc * 8] = v;
        }
        for (int i = tid; i < 1024; i += 256) {
            int j = i >> 4, cc = i & 15;
            *(uint4*)&Bs[j * 136 + cc * 8] = *(const uint4*)&g_bmat[j * 256 + kh * 128 + cc * 8];
        }
        __syncthreads();
        #pragma unroll
        for (int ks = 0; ks < 8; ks++) {
            const __half* ap = &As[(r0 + gid) * 136 + ks * 16 + 2 * tig];
            uint32_t a0 = *(const uint32_t*)ap;
            uint32_t a1 = *(const uint32_t*)(ap + 8 * 136);
            uint32_t a2 = *(const uint32_t*)(ap + 8);
            uint32_t a3 = *(const uint32_t*)(ap + 8 * 136 + 8);
            #pragma unroll
            for (int nt = 0; nt < 4; nt++) {
                const __half* bp = &Bs[(c0 + nt * 8 + gid) * 136 + ks * 16 + 2 * tig];
                uint32_t b0 = *(const uint32_t*)bp;
                uint32_t b1 = *(const uint32_t*)(bp + 8);
                mma16816(acc[nt], a0, a1, a2, a3, b0, b1);
            }
        }
        __syncthreads();
    }

    int node0 = base + r0 + gid, node1 = node0 + 8;
    #pragma unroll
    for (int nt = 0; nt < 4; nt++) {
        int col = c0 + nt * 8 + 2 * tig;
        float b0v = bias[col], b1v = bias[col + 1];
        if (node0 < n) {
            float2 xv = *(const float2*)&x[(size_t)node0 * 64 + col];
            float2 o;
            o.x = fmaxf(acc[nt][0] + b0v, 0.f) + xv.x;
            o.y = fmaxf(acc[nt][1] + b1v, 0.f) + xv.y;
            *(float2*)&out[(size_t)node0 * 64 + col] = o;
        }
        if (node1 < n) {
            float2 xv = *(const float2*)&x[(size_t)node1 * 64 + col];
            float2 o;
            o.x = fmaxf(acc[nt][2] + b0v, 0.f) + xv.x;
            o.y = fmaxf(acc[nt][3] + b1v, 0.f) + xv.y;
            *(float2*)&out[(size_t)node1 * 64 + col] = o;
        }
    }
}

// ---------------- launcher ----------------
extern "C" void kernel_launch(void* const* d_in, const int* in_sizes, int n_in,
                              void* d_out, int out_size) {
    const float* x        = (const float*)d_in[0];
    const int*   eidx     = (const int*)  d_in[1];
    const float* eattr    = (const float*)d_in[2];
    const float* W        = (const float*)d_in[3];
    const float* att_src  = (const float*)d_in[4];
    const float* att_dst  = (const float*)d_in[5];
    const float* lew      = (const float*)d_in[6];
    const float* att_edge = (const float*)d_in[7];
    const float* bias     = (const float*)d_in[8];
    float* out = (float*)d_out;

    int n = in_sizes[0] / 64;
    int E = in_sizes[2];
    const int* srcidx = eidx;
    const int* dstidx = eidx + E;
    int nb = (n + SCAN_B - 1) / SCAN_B;

    k_main   <<<512, 256>>>(x, eattr, W, att_src, att_dst, lew, att_edge, dstidx, n, E);
    k_scan   <<<nb, SCAN_B>>>(n, nb, E);
    k_scatter<<<(E + n + 255) / 256, 256>>>(srcidx, dstidx, eattr, E, n);
    k_agg    <<<(n + 7) / 8, 256>>>(n);
    k_outgemm<<<(n + 63) / 64, 256>>>(x, bias, out, n);
}

// round 10
// speedup vs baseline: 1.1793x; 1.1793x over previous
#include <cuda_runtime.h>
#include <cuda_fp16.h>
#include <cstdint>

// ---------------- problem caps ----------------
#define NMAX 50048
#define EMAX 800000
#define ETMAX (EMAX + NMAX)
#define SCAN_B 256
#define SCAN_G ((NMAX + SCAN_B - 1) / SCAN_B)

// ---------------- scratch (device globals; no runtime alloc) ----------------
__device__ __half g_xh[NMAX * 64];      // x in fp16 (6.4 MB, L2-resident gather table)
__device__ __half g_A[NMAX * 256];      // per-head aggregated x, head-stacked, fp16
__device__ __half g_bmat[64 * 256];     // rearranged W: bmat[j][h*64+kk] = W[kk][h*64+j]
__device__ float  g_va[512];            // va_src[256], va_dst[256]
__device__ float  g_asrc[NMAX * 4];
__device__ float  g_adst[NMAX * 4];
__device__ int    g_count[NMAX];
__device__ int    g_offset[NMAX];
__device__ int    g_cursor[NMAX];
__device__ int2   g_pay[ETMAX];         // {src, eav} per CSR slot
__device__ int    g_bsum[SCAN_G];
__device__ int    g_boff[SCAN_G];
__device__ int    g_done;               // self-resetting
__device__ float  g_mean_partial[512];
__device__ float  g_shead[4];
__device__ float  g_meanv;

// ---------------- kernels ----------------

// count init, x->fp16, W rearrange->fp16, mean partials; block 0: va/shead
__global__ void k_prep(const float* __restrict__ x, const float* __restrict__ ea,
                       const float* __restrict__ W, const float* __restrict__ att_src,
                       const float* __restrict__ att_dst, const float* __restrict__ lew,
                       const float* __restrict__ ae, int n, int E) {
    int t = threadIdx.x;
    int tid = blockIdx.x * blockDim.x + t;
    int stride = gridDim.x * blockDim.x;
    for (int i = tid; i < n; i += stride) g_count[i] = 1;          // self-loop
    int nh2 = n * 32;
    for (int i = tid; i < nh2; i += stride) {
        float2 v = ((const float2*)x)[i];
        ((half2*)g_xh)[i] = __floats2half2_rn(v.x, v.y);
    }
    for (int idx = tid; idx < 64 * 256; idx += stride) {
        int j = idx >> 8, k = idx & 255;
        int h = k >> 6, kk = k & 63;
        g_bmat[idx] = __float2half(W[kk * 256 + h * 64 + j]);
    }
    float s = 0.0f;
    for (int i = tid; i < E; i += stride) s += ea[i];
    #pragma unroll
    for (int o = 16; o; o >>= 1) s += __shfl_xor_sync(0xffffffffu, s, o);
    __shared__ float sm[8];
    int w = t >> 5;
    if ((t & 31) == 0) sm[w] = s;
    __syncthreads();
    if (t == 0) {
        float v = 0.0f;
        #pragma unroll
        for (int j = 0; j < 8; j++) v += sm[j];
        g_mean_partial[blockIdx.x] = v;
    }
    // block 0 extra: va_src/va_dst + shead (input-only dependencies)
    if (blockIdx.x == 0) {
        if (t < 4) {
            float p = 0.0f;
            for (int c = 0; c < 64; c++) p += lew[t * 64 + c] * ae[t * 64 + c];
            g_shead[t] = p;
        }
        int h = t >> 6, k = t & 63;
        const float* wrow = &W[k * 256 + h * 64];
        const float* as = &att_src[h * 64];
        const float* ad = &att_dst[h * 64];
        float vs = 0.0f, vd = 0.0f;
        #pragma unroll 8
        for (int c = 0; c < 64; c++) { float wv = wrow[c]; vs += wv * as[c]; vd += wv * ad[c]; }
        g_va[t] = vs;
        g_va[256 + t] = vd;
    }
}

// fused: degree counting atomics + per-node a_src/a_dst (warp per node via va, fp16 x)
__global__ void k_nc(const int* __restrict__ dstidx, int n, int E) {
    __shared__ float sva[512];
    int t = threadIdx.x;
    for (int i = t; i < 512; i += 256) sva[i] = g_va[i];
    __syncthreads();
    int tid = blockIdx.x * blockDim.x + t;
    int stride = gridDim.x * blockDim.x;
    for (int e = tid; e < E; e += stride) atomicAdd(&g_count[dstidx[e]], 1);
    int lane = t & 31;
    int warp = tid >> 5;
    int nwarp = stride >> 5;
    const half2* xh2 = (const half2*)g_xh;
    for (int node = warp; node < n; node += nwarp) {
        float2 xv = __half22float2(xh2[(size_t)node * 32 + lane]);
        float p[8];
        #pragma unroll
        for (int h = 0; h < 4; h++) {
            p[h]     = xv.x * sva[h * 64 + 2 * lane]       + xv.y * sva[h * 64 + 2 * lane + 1];
            p[4 + h] = xv.x * sva[256 + h * 64 + 2 * lane] + xv.y * sva[256 + h * 64 + 2 * lane + 1];
        }
        #pragma unroll
        for (int o = 16; o; o >>= 1) {
            #pragma unroll
            for (int j = 0; j < 8; j++) p[j] += __shfl_xor_sync(0xffffffffu, p[j], o);
        }
        if (lane == 0) {
            *(float4*)&g_asrc[node * 4] = make_float4(p[0], p[1], p[2], p[3]);
            *(float4*)&g_adst[node * 4] = make_float4(p[4], p[5], p[6], p[7]);
        }
    }
}

// fused scan phase A: per-block sums; last block scans sums, computes meanv,
// resets the done counter (deterministic across graph replays).
__global__ void k_scanA(int n, int nb, int E) {
    __shared__ int sm[8];
    int t = threadIdx.x;
    int i = blockIdx.x * SCAN_B + t;
    int v = (i < n) ? g_count[i] : 0;
    int r = v;
    #pragma unroll
    for (int o = 16; o; o >>= 1) r += __shfl_xor_sync(0xffffffffu, r, o);
    if ((t & 31) == 0) sm[t >> 5] = r;
    __syncthreads();
    if (t == 0) {
        int s = 0;
        #pragma unroll
        for (int j = 0; j < 8; j++) s += sm[j];
        g_bsum[blockIdx.x] = s;
    }
    __threadfence();
    __shared__ int lastf;
    if (t == 0) lastf = (atomicAdd(&g_done, 1) == (int)gridDim.x - 1) ? 1 : 0;
    __syncthreads();
    if (!lastf) return;

    // exclusive scan of nb block sums (nb <= 256)
    __shared__ int ss[SCAN_B];
    int u = (t < nb) ? *(volatile int*)&g_bsum[t] : 0;
    ss[t] = u;
    __syncthreads();
    #pragma unroll
    for (int o = 1; o < SCAN_B; o <<= 1) {
        int q = (t >= o) ? ss[t - o] : 0;
        __syncthreads();
        ss[t] += q;
        __syncthreads();
    }
    if (t < nb) g_boff[t] = ss[t] - u;

    // meanv from prep partials
    float m = g_mean_partial[t] + g_mean_partial[t + 256];
    #pragma unroll
    for (int o = 16; o; o >>= 1) m += __shfl_xor_sync(0xffffffffu, m, o);
    __shared__ float smf[8];
    if ((t & 31) == 0) smf[t >> 5] = m;
    __syncthreads();
    if (t == 0) {
        float s = 0.0f;
        #pragma unroll
        for (int j = 0; j < 8; j++) s += smf[j];
        g_meanv = s / (float)E;
        g_done = 0;                       // self-reset for next replay
    }
}

// scan phase B: per-block local exclusive scan + base -> offset/cursor
__global__ void k_scanB(int n) {
    __shared__ int ss[SCAN_B];
    int t = threadIdx.x;
    int i = blockIdx.x * SCAN_B + t;
    int v = (i < n) ? g_count[i] : 0;
    ss[t] = v;
    __syncthreads();
    #pragma unroll
    for (int o = 1; o < SCAN_B; o <<= 1) {
        int u = (t >= o) ? ss[t - o] : 0;
        __syncthreads();
        ss[t] += u;
        __syncthreads();
    }
    if (i < n) {
        int off = g_boff[blockIdx.x] + ss[t] - v;
        g_offset[i] = off;
        g_cursor[i] = off;
    }
}

// scatter: build fat CSR payload {src, eav} (sequential reads, one random 8B store)
__global__ void k_scatter(const int* __restrict__ srcidx, const int* __restrict__ dstidx,
                          const float* __restrict__ ea, int E, int n) {
    int e = blockIdx.x * blockDim.x + threadIdx.x;
    if (e >= E + n) return;
    int d, src; float eav;
    if (e < E) { d = dstidx[e]; src = srcidx[e]; eav = ea[e]; }
    else       { d = e - E;     src = e - E;     eav = g_meanv; }
    int pos = atomicAdd(&g_cursor[d], 1);
    g_pay[pos] = make_int2(src, __float_as_int(eav));
}

// warp per destination node: aggregate softmax-weighted x (fp16, 64 ch) per head.
// Weight-sums hoisted out of broadcast loop (were redundantly computed by all
// lanes); broadcast loop 2x unrolled for gather MLP.
__global__ void k_agg(int n, int E) {
    int gw = (blockIdx.x * blockDim.x + threadIdx.x) >> 5;
    int lane = threadIdx.x & 31;
    if (gw >= n) return;

    float sh0 = g_shead[0], sh1 = g_shead[1], sh2 = g_shead[2], sh3 = g_shead[3];
    float4 adv = *(const float4*)&g_adst[gw * 4];

    int start = g_offset[gw];
    int end = start + g_count[gw];

    float a00 = 0.f, a01 = 0.f, a10 = 0.f, a11 = 0.f;
    float a20 = 0.f, a21 = 0.f, a30 = 0.f, a31 = 0.f;
    float wsp0 = 0.f, wsp1 = 0.f, wsp2 = 0.f, wsp3 = 0.f;   // per-lane partial weight sums
    const half2* xh2 = (const half2*)g_xh;

    for (int base = start; base < end; base += 32) {
        int i = base + lane;
        float w0 = 0.f, w1 = 0.f, w2 = 0.f, w3 = 0.f;
        int src = 0;
        if (i < end) {
            int2 pv = g_pay[i];
            src = pv.x;
            float eav = __int_as_float(pv.y);
            float4 as = *(const float4*)&g_asrc[src * 4];
            float l0 = as.x + adv.x + eav * sh0; l0 = (l0 > 0.f) ? l0 : 0.2f * l0;
            float l1 = as.y + adv.y + eav * sh1; l1 = (l1 > 0.f) ? l1 : 0.2f * l1;
            float l2 = as.z + adv.z + eav * sh2; l2 = (l2 > 0.f) ? l2 : 0.2f * l2;
            float l3 = as.w + adv.w + eav * sh3; l3 = (l3 > 0.f) ? l3 : 0.2f * l3;
            w0 = __expf(l0); w1 = __expf(l1); w2 = __expf(l2); w3 = __expf(l3);
            wsp0 += w0; wsp1 += w1; wsp2 += w2; wsp3 += w3;
        }
        int cnt = min(32, end - base);
        int j = 0;
        for (; j + 1 < cnt; j += 2) {
            int   sA = __shfl_sync(0xffffffffu, src, j);
            int   sB = __shfl_sync(0xffffffffu, src, j + 1);
            float waA = __shfl_sync(0xffffffffu, w0, j);
            float wbA = __shfl_sync(0xffffffffu, w1, j);
            float wcA = __shfl_sync(0xffffffffu, w2, j);
            float wdA = __shfl_sync(0xffffffffu, w3, j);
            float waB = __shfl_sync(0xffffffffu, w0, j + 1);
            float wbB = __shfl_sync(0xffffffffu, w1, j + 1);
            float wcB = __shfl_sync(0xffffffffu, w2, j + 1);
            float wdB = __shfl_sync(0xffffffffu, w3, j + 1);
            float2 fA = __half22float2(xh2[(size_t)sA * 32 + lane]);
            float2 fB = __half22float2(xh2[(size_t)sB * 32 + lane]);
            a00 += waA * fA.x; a01 += waA * fA.y;
            a10 += wbA * fA.x; a11 += wbA * fA.y;
            a20 += wcA * fA.x; a21 += wcA * fA.y;
            a30 += wdA * fA.x; a31 += wdA * fA.y;
            a00 += waB * fB.x; a01 += waB * fB.y;
            a10 += wbB * fB.x; a11 += wbB * fB.y;
            a20 += wcB * fB.x; a21 += wcB * fB.y;
            a30 += wdB * fB.x; a31 += wdB * fB.y;
        }
        if (j < cnt) {
            int   sA = __shfl_sync(0xffffffffu, src, j);
            float waA = __shfl_sync(0xffffffffu, w0, j);
            float wbA = __shfl_sync(0xffffffffu, w1, j);
            float wcA = __shfl_sync(0xffffffffu, w2, j);
            float wdA = __shfl_sync(0xffffffffu, w3, j);
            float2 fA = __half22float2(xh2[(size_t)sA * 32 + lane]);
            a00 += waA * fA.x; a01 += waA * fA.y;
            a10 += wbA * fA.x; a11 += wbA * fA.y;
            a20 += wcA * fA.x; a21 += wcA * fA.y;
            a30 += wdA * fA.x; a31 += wdA * fA.y;
        }
    }

    // butterfly-reduce the per-lane weight sums (all lanes end with totals)
    #pragma unroll
    for (int o = 16; o; o >>= 1) {
        wsp0 += __shfl_xor_sync(0xffffffffu, wsp0, o);
        wsp1 += __shfl_xor_sync(0xffffffffu, wsp1, o);
        wsp2 += __shfl_xor_sync(0xffffffffu, wsp2, o);
        wsp3 += __shfl_xor_sync(0xffffffffu, wsp3, o);
    }

    float i0 = 0.25f / (wsp0 + 1e-16f);   // fold 1/4 head-mean into normalize
    float i1 = 0.25f / (wsp1 + 1e-16f);
    float i2 = 0.25f / (wsp2 + 1e-16f);
    float i3 = 0.25f / (wsp3 + 1e-16f);

    half2* A2 = (half2*)g_A + (size_t)gw * 128 + lane;
    A2[0]  = __floats2half2_rn(a00 * i0, a01 * i0);
    A2[32] = __floats2half2_rn(a10 * i1, a11 * i1);
    A2[64] = __floats2half2_rn(a20 * i2, a21 * i2);
    A2[96] = __floats2half2_rn(a30 * i3, a31 * i3);
}

__device__ __forceinline__ void mma16816(float* c, uint32_t a0, uint32_t a1,
                                         uint32_t a2, uint32_t a3,
                                         uint32_t b0, uint32_t b1) {
    asm("mma.sync.aligned.m16n8k16.row.col.f32.f16.f16.f32 "
        "{%0,%1,%2,%3}, {%4,%5,%6,%7}, {%8,%9}, {%0,%1,%2,%3};"
        : "+f"(c[0]), "+f"(c[1]), "+f"(c[2]), "+f"(c[3])
        : "r"(a0), "r"(a1), "r"(a2), "r"(a3), "r"(b0), "r"(b1));
}

// out = relu( A @ bmat + bias ) + x.
__global__ void k_outgemm(const float* __restrict__ x, const float* __restrict__ bias,
                          float* __restrict__ out, int n) {
    __shared__ __half As[64 * 136];
    __shared__ __half Bs[64 * 136];
    int tid = threadIdx.x;
    int base = blockIdx.x * 64;
    int w = tid >> 5, lane = tid & 31;
    int gid = lane >> 2, tig = lane & 3;
    int r0 = (w & 3) * 16, c0 = (w >> 2) * 32;

    float acc[4][4];
    #pragma unroll
    for (int nt = 0; nt < 4; nt++)
        #pragma unroll
        for (int j = 0; j < 4; j++) acc[nt][j] = 0.0f;

    #pragma unroll
    for (int kh = 0; kh < 2; kh++) {
        for (int i = tid; i < 1024; i += 256) {
            int r = i >> 4, cc = i & 15;
            int node = base + r;
            uint4 v = (node < n) ? *(const uint4*)&g_A[(size_t)node * 256 + kh * 128 + cc * 8]
                                 : make_uint4(0u, 0u, 0u, 0u);
            *(uint4*)&As[r * 136 + cc * 8] = v;
        }
        for (int i = tid; i < 1024; i += 256) {
            int j = i >> 4, cc = i & 15;
            *(uint4*)&Bs[j * 136 + cc * 8] = *(const uint4*)&g_bmat[j * 256 + kh * 128 + cc * 8];
        }
        __syncthreads();
        #pragma unroll
        for (int ks = 0; ks < 8; ks++) {
            const __half* ap = &As[(r0 + gid) * 136 + ks * 16 + 2 * tig];
            uint32_t a0 = *(const uint32_t*)ap;
            uint32_t a1 = *(const uint32_t*)(ap + 8 * 136);
            uint32_t a2 = *(const uint32_t*)(ap + 8);
            uint32_t a3 = *(const uint32_t*)(ap + 8 * 136 + 8);
            #pragma unroll
            for (int nt = 0; nt < 4; nt++) {
                const __half* bp = &Bs[(c0 + nt * 8 + gid) * 136 + ks * 16 + 2 * tig];
                uint32_t b0 = *(const uint32_t*)bp;
                uint32_t b1 = *(const uint32_t*)(bp + 8);
                mma16816(acc[nt], a0, a1, a2, a3, b0, b1);
            }
        }
        __syncthreads();
    }

    int node0 = base + r0 + gid, node1 = node0 + 8;
    #pragma unroll
    for (int nt = 0; nt < 4; nt++) {
        int col = c0 + nt * 8 + 2 * tig;
        float b0v = bias[col], b1v = bias[col + 1];
        if (node0 < n) {
            float2 xv = *(const float2*)&x[(size_t)node0 * 64 + col];
            float2 o;
            o.x = fmaxf(acc[nt][0] + b0v, 0.f) + xv.x;
            o.y = fmaxf(acc[nt][1] + b1v, 0.f) + xv.y;
            *(float2*)&out[(size_t)node0 * 64 + col] = o;
        }
        if (node1 < n) {
            float2 xv = *(const float2*)&x[(size_t)node1 * 64 + col];
            float2 o;
            o.x = fmaxf(acc[nt][2] + b0v, 0.f) + xv.x;
            o.y = fmaxf(acc[nt][3] + b1v, 0.f) + xv.y;
            *(float2*)&out[(size_t)node1 * 64 + col] = o;
        }
    }
}

// ---------------- launcher ----------------
extern "C" void kernel_launch(void* const* d_in, const int* in_sizes, int n_in,
                              void* d_out, int out_size) {
    const float* x        = (const float*)d_in[0];
    const int*   eidx     = (const int*)  d_in[1];
    const float* eattr    = (const float*)d_in[2];
    const float* W        = (const float*)d_in[3];
    const float* att_src  = (const float*)d_in[4];
    const float* att_dst  = (const float*)d_in[5];
    const float* lew      = (const float*)d_in[6];
    const float* att_edge = (const float*)d_in[7];
    const float* bias     = (const float*)d_in[8];
    float* out = (float*)d_out;

    int n = in_sizes[0] / 64;
    int E = in_sizes[2];
    const int* srcidx = eidx;
    const int* dstidx = eidx + E;
    int nb = (n + SCAN_B - 1) / SCAN_B;

    k_prep   <<<512, 256>>>(x, eattr, W, att_src, att_dst, lew, att_edge, n, E);
    k_nc     <<<(E + 255) / 256, 256>>>(dstidx, n, E);
    k_scanA  <<<nb, SCAN_B>>>(n, nb, E);
    k_scanB  <<<nb, SCAN_B>>>(n);
    k_scatter<<<(E + n + 255) / 256, 256>>>(srcidx, dstidx, eattr, E, n);
    k_agg    <<<(n + 7) / 8, 256>>>(n, E);
    k_outgemm<<<(n + 63) / 64, 256>>>(x, bias, out, n);
}

// round 11
// speedup vs baseline: 1.2179x; 1.0327x over previous
#include <cuda_runtime.h>
#include <cuda_fp16.h>
#include <cstdint>

// ---------------- problem caps ----------------
#define NMAX 50048
#define EMAX 800000
#define ETMAX (EMAX + NMAX)
#define SCAN_B 256
#define SCAN_G ((NMAX + SCAN_B - 1) / SCAN_B)

// ---------------- scratch (device globals; no runtime alloc) ----------------
__device__ __half g_xh[NMAX * 64];      // x in fp16 (6.4 MB, L2-resident gather table)
__device__ __half g_A[NMAX * 256];      // per-head aggregated x, head-stacked, fp16
__device__ __half g_bmat[64 * 256];     // rearranged W: bmat[j][h*64+kk] = W[kk][h*64+j]
__device__ float  g_va[512];            // va_src[256], va_dst[256]
__device__ float  g_asrc[NMAX * 4];
__device__ float  g_adst[NMAX * 4];
__device__ int    g_count[NMAX];
__device__ int    g_offset[NMAX];
__device__ int    g_cursor[NMAX];
__device__ int2   g_pay[ETMAX];         // {src, eav} per CSR slot
__device__ int    g_bsum[SCAN_G];
__device__ unsigned long long g_pkt[SCAN_G];   // {flag,base}; self-cleaning per replay
__device__ int    g_done;               // self-resetting
__device__ float  g_mean_partial[512];
__device__ float  g_shead[4];
__device__ float  g_meanv;

// ---------------- kernels ----------------

// count init, x->fp16, W rearrange->fp16, mean partials; block 0: va/shead
__global__ void k_prep(const float* __restrict__ x, const float* __restrict__ ea,
                       const float* __restrict__ W, const float* __restrict__ att_src,
                       const float* __restrict__ att_dst, const float* __restrict__ lew,
                       const float* __restrict__ ae, int n, int E) {
    int t = threadIdx.x;
    int tid = blockIdx.x * blockDim.x + t;
    int stride = gridDim.x * blockDim.x;
    for (int i = tid; i < n; i += stride) g_count[i] = 1;          // self-loop
    int nh2 = n * 32;
    for (int i = tid; i < nh2; i += stride) {
        float2 v = ((const float2*)x)[i];
        ((half2*)g_xh)[i] = __floats2half2_rn(v.x, v.y);
    }
    for (int idx = tid; idx < 64 * 256; idx += stride) {
        int j = idx >> 8, k = idx & 255;
        int h = k >> 6, kk = k & 63;
        g_bmat[idx] = __float2half(W[kk * 256 + h * 64 + j]);
    }
    float s = 0.0f;
    for (int i = tid; i < E; i += stride) s += ea[i];
    #pragma unroll
    for (int o = 16; o; o >>= 1) s += __shfl_xor_sync(0xffffffffu, s, o);
    __shared__ float sm[8];
    int w = t >> 5;
    if ((t & 31) == 0) sm[w] = s;
    __syncthreads();
    if (t == 0) {
        float v = 0.0f;
        #pragma unroll
        for (int j = 0; j < 8; j++) v += sm[j];
        g_mean_partial[blockIdx.x] = v;
    }
    // block 0 extra: va_src/va_dst + shead (input-only dependencies)
    if (blockIdx.x == 0) {
        if (t < 4) {
            float p = 0.0f;
            for (int c = 0; c < 64; c++) p += lew[t * 64 + c] * ae[t * 64 + c];
            g_shead[t] = p;
        }
        int h = t >> 6, k = t & 63;
        const float* wrow = &W[k * 256 + h * 64];
        const float* as = &att_src[h * 64];
        const float* ad = &att_dst[h * 64];
        float vs = 0.0f, vd = 0.0f;
        #pragma unroll 8
        for (int c = 0; c < 64; c++) { float wv = wrow[c]; vs += wv * as[c]; vd += wv * ad[c]; }
        g_va[t] = vs;
        g_va[256 + t] = vd;
    }
}

// fused: degree counting atomics + per-node a_src/a_dst (warp per node via va, fp16 x)
__global__ void k_nc(const int* __restrict__ dstidx, int n, int E) {
    __shared__ float sva[512];
    int t = threadIdx.x;
    for (int i = t; i < 512; i += 256) sva[i] = g_va[i];
    __syncthreads();
    int tid = blockIdx.x * blockDim.x + t;
    int stride = gridDim.x * blockDim.x;
    for (int e = tid; e < E; e += stride) atomicAdd(&g_count[dstidx[e]], 1);
    int lane = t & 31;
    int warp = tid >> 5;
    int nwarp = stride >> 5;
    const half2* xh2 = (const half2*)g_xh;
    for (int node = warp; node < n; node += nwarp) {
        float2 xv = __half22float2(xh2[(size_t)node * 32 + lane]);
        float p[8];
        #pragma unroll
        for (int h = 0; h < 4; h++) {
            p[h]     = xv.x * sva[h * 64 + 2 * lane]       + xv.y * sva[h * 64 + 2 * lane + 1];
            p[4 + h] = xv.x * sva[256 + h * 64 + 2 * lane] + xv.y * sva[256 + h * 64 + 2 * lane + 1];
        }
        #pragma unroll
        for (int o = 16; o; o >>= 1) {
            #pragma unroll
            for (int j = 0; j < 8; j++) p[j] += __shfl_xor_sync(0xffffffffu, p[j], o);
        }
        if (lane == 0) {
            *(float4*)&g_asrc[node * 4] = make_float4(p[0], p[1], p[2], p[3]);
            *(float4*)&g_adst[node * 4] = make_float4(p[4], p[5], p[6], p[7]);
        }
    }
}

// Fused single-kernel scan: per-block local inclusive scan; LAST-arriving block
// scans the nb block sums and publishes each block's base as a packed
// {flag,base} 64-bit packet. Every other block spins on ITS OWN packet only
// (single-hop, no serial lookback) and resets it for the next graph replay.
__global__ void k_scan(int n, int nb, int E) {
    __shared__ int ss[SCAN_B];
    __shared__ int sbase;
    __shared__ int lastf;
    int t = threadIdx.x, bid = blockIdx.x;
    int i = bid * SCAN_B + t;
    int v = (i < n) ? g_count[i] : 0;
    ss[t] = v;
    __syncthreads();
    #pragma unroll
    for (int o = 1; o < SCAN_B; o <<= 1) {
        int u = (t >= o) ? ss[t - o] : 0;
        __syncthreads();
        ss[t] += u;
        __syncthreads();
    }
    int total = ss[SCAN_B - 1];

    if (t == 0) {
        g_bsum[bid] = total;
        __threadfence();
        lastf = (atomicAdd(&g_done, 1) == nb - 1) ? 1 : 0;
    }
    __syncthreads();

    if (lastf) {
        // last block: exclusive scan of nb block sums, publish packets
        __shared__ int sb[SCAN_B];
        int u = (t < nb) ? *(volatile int*)&g_bsum[t] : 0;
        sb[t] = u;
        __syncthreads();
        #pragma unroll
        for (int o = 1; o < SCAN_B; o <<= 1) {
            int q = (t >= o) ? sb[t - o] : 0;
            __syncthreads();
            sb[t] += q;
            __syncthreads();
        }
        if (t < nb && t != bid) {
            *(volatile unsigned long long*)&g_pkt[t] =
                (1ULL << 32) | (unsigned long long)(unsigned)(sb[t] - u);
        }
        if (t == bid) sbase = sb[t] - u;
        // meanv from prep partials + done reset
        float m = g_mean_partial[t] + g_mean_partial[t + 256];
        #pragma unroll
        for (int o = 16; o; o >>= 1) m += __shfl_xor_sync(0xffffffffu, m, o);
        __shared__ float smf[8];
        if ((t & 31) == 0) smf[t >> 5] = m;
        __syncthreads();
        if (t == 0) {
            float s = 0.0f;
            #pragma unroll
            for (int j = 0; j < 8; j++) s += smf[j];
            g_meanv = s / (float)E;
            g_done = 0;                                    // replay-safe reset
        }
        __syncthreads();
    } else {
        if (t == 0) {
            unsigned long long p;
            do { p = *(volatile unsigned long long*)&g_pkt[bid]; } while (!(p >> 32));
            *(volatile unsigned long long*)&g_pkt[bid] = 0ULL;   // self-clean
            sbase = (int)(unsigned)p;
        }
        __syncthreads();
    }

    int base = sbase;
    if (i < n) {
        int off = base + ss[t] - v;
        g_offset[i] = off;
        g_cursor[i] = off;
    }
}

// scatter: build fat CSR payload {src, eav} (sequential reads, one random 8B store)
__global__ void k_scatter(const int* __restrict__ srcidx, const int* __restrict__ dstidx,
                          const float* __restrict__ ea, int E, int n) {
    int e = blockIdx.x * blockDim.x + threadIdx.x;
    if (e >= E + n) return;
    int d, src; float eav;
    if (e < E) { d = dstidx[e]; src = srcidx[e]; eav = ea[e]; }
    else       { d = e - E;     src = e - E;     eav = g_meanv; }
    int pos = atomicAdd(&g_cursor[d], 1);
    g_pay[pos] = make_int2(src, __float_as_int(eav));
}

// warp per destination node (round-6 body verbatim); 128-thr blocks +
// launch_bounds for higher occupancy (latency-exposure bound per R9 profile).
__global__ void __launch_bounds__(128, 12) k_agg(int n, int E) {
    int gw = (blockIdx.x * blockDim.x + threadIdx.x) >> 5;
    int lane = threadIdx.x & 31;
    if (gw >= n) return;

    float sh0 = g_shead[0], sh1 = g_shead[1], sh2 = g_shead[2], sh3 = g_shead[3];
    float4 adv = *(const float4*)&g_adst[gw * 4];

    int start = g_offset[gw];
    int end = start + g_count[gw];

    float a00 = 0.f, a01 = 0.f, a10 = 0.f, a11 = 0.f;
    float a20 = 0.f, a21 = 0.f, a30 = 0.f, a31 = 0.f;
    float ws0 = 0.f, ws1 = 0.f, ws2 = 0.f, ws3 = 0.f;
    const half2* xh2 = (const half2*)g_xh;

    for (int base = start; base < end; base += 32) {
        int i = base + lane;
        float w0 = 0.f, w1 = 0.f, w2 = 0.f, w3 = 0.f;
        int src = 0;
        if (i < end) {
            int2 pv = g_pay[i];
            src = pv.x;
            float eav = __int_as_float(pv.y);
            float4 as = *(const float4*)&g_asrc[src * 4];
            float l0 = as.x + adv.x + eav * sh0; l0 = (l0 > 0.f) ? l0 : 0.2f * l0;
            float l1 = as.y + adv.y + eav * sh1; l1 = (l1 > 0.f) ? l1 : 0.2f * l1;
            float l2 = as.z + adv.z + eav * sh2; l2 = (l2 > 0.f) ? l2 : 0.2f * l2;
            float l3 = as.w + adv.w + eav * sh3; l3 = (l3 > 0.f) ? l3 : 0.2f * l3;
            w0 = __expf(l0); w1 = __expf(l1); w2 = __expf(l2); w3 = __expf(l3);
        }
        int cnt = min(32, end - base);
        for (int j = 0; j < cnt; j++) {
            int   s  = __shfl_sync(0xffffffffu, src, j);
            float wa = __shfl_sync(0xffffffffu, w0,  j);
            float wb = __shfl_sync(0xffffffffu, w1,  j);
            float wc = __shfl_sync(0xffffffffu, w2,  j);
            float wd = __shfl_sync(0xffffffffu, w3,  j);
            float2 f = __half22float2(xh2[(size_t)s * 32 + lane]);
            a00 += wa * f.x; a01 += wa * f.y; ws0 += wa;
            a10 += wb * f.x; a11 += wb * f.y; ws1 += wb;
            a20 += wc * f.x; a21 += wc * f.y; ws2 += wc;
            a30 += wd * f.x; a31 += wd * f.y; ws3 += wd;
        }
    }

    float i0 = 0.25f / (ws0 + 1e-16f);   // fold 1/4 head-mean into normalize
    float i1 = 0.25f / (ws1 + 1e-16f);
    float i2 = 0.25f / (ws2 + 1e-16f);
    float i3 = 0.25f / (ws3 + 1e-16f);

    half2* A2 = (half2*)g_A + (size_t)gw * 128 + lane;
    A2[0]  = __floats2half2_rn(a00 * i0, a01 * i0);
    A2[32] = __floats2half2_rn(a10 * i1, a11 * i1);
    A2[64] = __floats2half2_rn(a20 * i2, a21 * i2);
    A2[96] = __floats2half2_rn(a30 * i3, a31 * i3);
}

__device__ __forceinline__ void mma16816(float* c, uint32_t a0, uint32_t a1,
                                         uint32_t a2, uint32_t a3,
                                         uint32_t b0, uint32_t b1) {
    asm("mma.sync.aligned.m16n8k16.row.col.f32.f16.f16.f32 "
        "{%0,%1,%2,%3}, {%4,%5,%6,%7}, {%8,%9}, {%0,%1,%2,%3};"
        : "+f"(c[0]), "+f"(c[1]), "+f"(c[2]), "+f"(c[3])
        : "r"(a0), "r"(a1), "r"(a2), "r"(a3), "r"(b0), "r"(b1));
}

// out = relu( A @ bmat + bias ) + x.
__global__ void k_outgemm(const float* __restrict__ x, const float* __restrict__ bias,
                          float* __restrict__ out, int n) {
    __shared__ __half As[64 * 136];
    __shared__ __half Bs[64 * 136];
    int tid = threadIdx.x;
    int base = blockIdx.x * 64;
    int w = tid >> 5, lane = tid & 31;
    int gid = lane >> 2, tig = lane & 3;
    int r0 = (w & 3) * 16, c0 = (w >> 2) * 32;

    float acc[4][4];
    #pragma unroll
    for (int nt = 0; nt < 4; nt++)
        #pragma unroll
        for (int j = 0; j < 4; j++) acc[nt][j] = 0.0f;

    #pragma unroll
    for (int kh = 0; kh < 2; kh++) {
        for (int i = tid; i < 1024; i += 256) {
            int r = i >> 4, cc = i & 15;
            int node = base + r;
            uint4 v = (node < n) ? *(const uint4*)&g_A[(size_t)node * 256 + kh * 128 + cc * 8]
                                 : make_uint4(0u, 0u, 0u, 0u);
            *(uint4*)&As[r * 136 + cc * 8] = v;
        }
        for (int i = tid; i < 1024; i += 256) {
            int j = i >> 4, cc = i & 15;
            *(uint4*)&Bs[j * 136 + cc * 8] = *(const uint4*)&g_bmat[j * 256 + kh * 128 + cc * 8];
        }
        __syncthreads();
        #pragma unroll
        for (int ks = 0; ks < 8; ks++) {
            const __half* ap = &As[(r0 + gid) * 136 + ks * 16 + 2 * tig];
            uint32_t a0 = *(const uint32_t*)ap;
            uint32_t a1 = *(const uint32_t*)(ap + 8 * 136);
            uint32_t a2 = *(const uint32_t*)(ap + 8);
            uint32_t a3 = *(const uint32_t*)(ap + 8 * 136 + 8);
            #pragma unroll
            for (int nt = 0; nt < 4; nt++) {
                const __half* bp = &Bs[(c0 + nt * 8 + gid) * 136 + ks * 16 + 2 * tig];
                uint32_t b0 = *(const uint32_t*)bp;
                uint32_t b1 = *(const uint32_t*)(bp + 8);
                mma16816(acc[nt], a0, a1, a2, a3, b0, b1);
            }
        }
        __syncthreads();
    }

    int node0 = base + r0 + gid, node1 = node0 + 8;
    #pragma unroll
    for (int nt = 0; nt < 4; nt++) {
        int col = c0 + nt * 8 + 2 * tig;
        float b0v = bias[col], b1v = bias[col + 1];
        if (node0 < n) {
            float2 xv = *(const float2*)&x[(size_t)node0 * 64 + col];
            float2 o;
            o.x = fmaxf(acc[nt][0] + b0v, 0.f) + xv.x;
            o.y = fmaxf(acc[nt][1] + b1v, 0.f) + xv.y;
            *(float2*)&out[(size_t)node0 * 64 + col] = o;
        }
        if (node1 < n) {
            float2 xv = *(const float2*)&x[(size_t)node1 * 64 + col];
            float2 o;
            o.x = fmaxf(acc[nt][2] + b0v, 0.f) + xv.x;
            o.y = fmaxf(acc[nt][3] + b1v, 0.f) + xv.y;
            *(float2*)&out[(size_t)node1 * 64 + col] = o;
        }
    }
}

// ---------------- launcher ----------------
extern "C" void kernel_launch(void* const* d_in, const int* in_sizes, int n_in,
                              void* d_out, int out_size) {
    const float* x        = (const float*)d_in[0];
    const int*   eidx     = (const int*)  d_in[1];
    const float* eattr    = (const float*)d_in[2];
    const float* W        = (const float*)d_in[3];
    const float* att_src  = (const float*)d_in[4];
    const float* att_dst  = (const float*)d_in[5];
    const float* lew      = (const float*)d_in[6];
    const float* att_edge = (const float*)d_in[7];
    const float* bias     = (const float*)d_in[8];
    float* out = (float*)d_out;

    int n = in_sizes[0] / 64;
    int E = in_sizes[2];
    const int* srcidx = eidx;
    const int* dstidx = eidx + E;
    int nb = (n + SCAN_B - 1) / SCAN_B;

    k_prep   <<<512, 256>>>(x, eattr, W, att_src, att_dst, lew, att_edge, n, E);
    k_nc     <<<(E + 255) / 256, 256>>>(dstidx, n, E);
    k_scan   <<<nb, SCAN_B>>>(n, nb, E);
    k_scatter<<<(E + n + 255) / 256, 256>>>(srcidx, dstidx, eattr, E, n);
    k_agg    <<<(n + 3) / 4, 128>>>(n, E);
    k_outgemm<<<(n + 63) / 64, 256>>>(x, bias, out, n);
}

// round 12
// speedup vs baseline: 1.2683x; 1.0414x over previous
#include <cuda_runtime.h>
#include <cuda_fp16.h>
#include <cstdint>

// ---------------- problem caps ----------------
#define NMAX 50048
#define EMAX 800000
#define ETMAX (EMAX + NMAX)
#define SCAN_B 256
#define SCAN_G ((NMAX + SCAN_B - 1) / SCAN_B)

// ---------------- scratch (device globals; no runtime alloc) ----------------
__device__ __half g_xh[NMAX * 64];      // x in fp16 (6.4 MB, L2-resident gather table)
__device__ __half g_A[NMAX * 256];      // per-head aggregated x, head-stacked, fp16
__device__ __half g_bmat[64 * 256];     // rearranged W: bmat[j][h*64+kk] = W[kk][h*64+j]
__device__ float  g_va[512];            // va_src[256], va_dst[256]
__device__ float  g_asrc[NMAX * 4];
__device__ float  g_adst[NMAX * 4];
__device__ int    g_count[NMAX];
__device__ int    g_offset[NMAX];
__device__ int    g_rank[EMAX];         // per-edge rank within its destination
__device__ int2   g_pay[ETMAX];         // {src, eav} per CSR slot
__device__ int    g_bsum[SCAN_G];
__device__ unsigned long long g_pkt[SCAN_G];   // {flag,base}; self-cleaning per replay
__device__ int    g_done;               // self-resetting
__device__ float  g_mean_partial[512];
__device__ float  g_shead[4];
__device__ float  g_meanv;

// ---------------- kernels ----------------

// count init, x->fp16, W rearrange->fp16, mean partials; block 0: va/shead
__global__ void k_prep(const float* __restrict__ x, const float* __restrict__ ea,
                       const float* __restrict__ W, const float* __restrict__ att_src,
                       const float* __restrict__ att_dst, const float* __restrict__ lew,
                       const float* __restrict__ ae, int n, int E) {
    int t = threadIdx.x;
    int tid = blockIdx.x * blockDim.x + t;
    int stride = gridDim.x * blockDim.x;
    for (int i = tid; i < n; i += stride) g_count[i] = 1;          // self-loop
    int nh2 = n * 32;
    for (int i = tid; i < nh2; i += stride) {
        float2 v = ((const float2*)x)[i];
        ((half2*)g_xh)[i] = __floats2half2_rn(v.x, v.y);
    }
    for (int idx = tid; idx < 64 * 256; idx += stride) {
        int j = idx >> 8, k = idx & 255;
        int h = k >> 6, kk = k & 63;
        g_bmat[idx] = __float2half(W[kk * 256 + h * 64 + j]);
    }
    float s = 0.0f;
    for (int i = tid; i < E; i += stride) s += ea[i];
    #pragma unroll
    for (int o = 16; o; o >>= 1) s += __shfl_xor_sync(0xffffffffu, s, o);
    __shared__ float sm[8];
    int w = t >> 5;
    if ((t & 31) == 0) sm[w] = s;
    __syncthreads();
    if (t == 0) {
        float v = 0.0f;
        #pragma unroll
        for (int j = 0; j < 8; j++) v += sm[j];
        g_mean_partial[blockIdx.x] = v;
    }
    // block 0 extra: va_src/va_dst + shead (input-only dependencies)
    if (blockIdx.x == 0) {
        if (t < 4) {
            float p = 0.0f;
            for (int c = 0; c < 64; c++) p += lew[t * 64 + c] * ae[t * 64 + c];
            g_shead[t] = p;
        }
        int h = t >> 6, k = t & 63;
        const float* wrow = &W[k * 256 + h * 64];
        const float* as = &att_src[h * 64];
        const float* ad = &att_dst[h * 64];
        float vs = 0.0f, vd = 0.0f;
        #pragma unroll 8
        for (int c = 0; c < 64; c++) { float wv = wrow[c]; vs += wv * as[c]; vd += wv * ad[c]; }
        g_va[t] = vs;
        g_va[256 + t] = vd;
    }
}

// fused: degree counting atomics (return value = per-dst rank, stored
// sequentially) + per-node a_src/a_dst (warp per node via va, fp16 x)
__global__ void k_nc(const int* __restrict__ dstidx, int n, int E) {
    __shared__ float sva[512];
    int t = threadIdx.x;
    for (int i = t; i < 512; i += 256) sva[i] = g_va[i];
    __syncthreads();
    int tid = blockIdx.x * blockDim.x + t;
    int stride = gridDim.x * blockDim.x;
    for (int e = tid; e < E; e += stride)
        g_rank[e] = atomicAdd(&g_count[dstidx[e]], 1);   // rank in [1, deg]
    int lane = t & 31;
    int warp = tid >> 5;
    int nwarp = stride >> 5;
    const half2* xh2 = (const half2*)g_xh;
    for (int node = warp; node < n; node += nwarp) {
        float2 xv = __half22float2(xh2[(size_t)node * 32 + lane]);
        float p[8];
        #pragma unroll
        for (int h = 0; h < 4; h++) {
            p[h]     = xv.x * sva[h * 64 + 2 * lane]       + xv.y * sva[h * 64 + 2 * lane + 1];
            p[4 + h] = xv.x * sva[256 + h * 64 + 2 * lane] + xv.y * sva[256 + h * 64 + 2 * lane + 1];
        }
        #pragma unroll
        for (int o = 16; o; o >>= 1) {
            #pragma unroll
            for (int j = 0; j < 8; j++) p[j] += __shfl_xor_sync(0xffffffffu, p[j], o);
        }
        if (lane == 0) {
            *(float4*)&g_asrc[node * 4] = make_float4(p[0], p[1], p[2], p[3]);
            *(float4*)&g_adst[node * 4] = make_float4(p[4], p[5], p[6], p[7]);
        }
    }
}

// Fused single-kernel scan: per-block local inclusive scan; LAST-arriving block
// scans the nb block sums and publishes each block's base as a packed
// {flag,base} 64-bit packet. Every other block spins on ITS OWN packet only
// (single-hop) and resets it for the next graph replay.
__global__ void k_scan(int n, int nb, int E) {
    __shared__ int ss[SCAN_B];
    __shared__ int sbase;
    __shared__ int lastf;
    int t = threadIdx.x, bid = blockIdx.x;
    int i = bid * SCAN_B + t;
    int v = (i < n) ? g_count[i] : 0;
    ss[t] = v;
    __syncthreads();
    #pragma unroll
    for (int o = 1; o < SCAN_B; o <<= 1) {
        int u = (t >= o) ? ss[t - o] : 0;
        __syncthreads();
        ss[t] += u;
        __syncthreads();
    }
    int total = ss[SCAN_B - 1];

    if (t == 0) {
        g_bsum[bid] = total;
        __threadfence();
        lastf = (atomicAdd(&g_done, 1) == nb - 1) ? 1 : 0;
    }
    __syncthreads();

    if (lastf) {
        __shared__ int sb[SCAN_B];
        int u = (t < nb) ? *(volatile int*)&g_bsum[t] : 0;
        sb[t] = u;
        __syncthreads();
        #pragma unroll
        for (int o = 1; o < SCAN_B; o <<= 1) {
            int q = (t >= o) ? sb[t - o] : 0;
            __syncthreads();
            sb[t] += q;
            __syncthreads();
        }
        if (t < nb && t != bid) {
            *(volatile unsigned long long*)&g_pkt[t] =
                (1ULL << 32) | (unsigned long long)(unsigned)(sb[t] - u);
        }
        if (t == bid) sbase = sb[t] - u;
        // meanv from prep partials + done reset
        float m = g_mean_partial[t] + g_mean_partial[t + 256];
        #pragma unroll
        for (int o = 16; o; o >>= 1) m += __shfl_xor_sync(0xffffffffu, m, o);
        __shared__ float smf[8];
        if ((t & 31) == 0) smf[t >> 5] = m;
        __syncthreads();
        if (t == 0) {
            float s = 0.0f;
            #pragma unroll
            for (int j = 0; j < 8; j++) s += smf[j];
            g_meanv = s / (float)E;
            g_done = 0;                                    // replay-safe reset
        }
        __syncthreads();
    } else {
        if (t == 0) {
            unsigned long long p;
            do { p = *(volatile unsigned long long*)&g_pkt[bid]; } while (!(p >> 32));
            *(volatile unsigned long long*)&g_pkt[bid] = 0ULL;   // self-clean
            sbase = (int)(unsigned)p;
        }
        __syncthreads();
    }

    int base = sbase;
    if (i < n) g_offset[i] = base + ss[t] - v;
}

// scatter: ATOMIC-FREE. pos = offset[dst] + rank (self-loop takes rank 0).
// 4 coalesced reads + 1 random 8B store per edge.
__global__ void k_scatter(const int* __restrict__ srcidx, const int* __restrict__ dstidx,
                          const float* __restrict__ ea, int E, int n) {
    int e = blockIdx.x * blockDim.x + threadIdx.x;
    if (e >= E + n) return;
    int d, src, r; float eav;
    if (e < E) { d = dstidx[e]; src = srcidx[e]; eav = ea[e]; r = g_rank[e]; }
    else       { d = e - E;     src = e - E;     eav = g_meanv; r = 0; }
    int pos = g_offset[d] + r;
    g_pay[pos] = make_int2(src, __float_as_int(eav));
}

// warp per destination node: aggregate softmax-weighted x (fp16, 64 ch) per
// head. Round-6 body verbatim (verified local optimum).
__global__ void k_agg(int n, int E) {
    int gw = (blockIdx.x * blockDim.x + threadIdx.x) >> 5;
    int lane = threadIdx.x & 31;
    if (gw >= n) return;

    float sh0 = g_shead[0], sh1 = g_shead[1], sh2 = g_shead[2], sh3 = g_shead[3];
    float4 adv = *(const float4*)&g_adst[gw * 4];

    int start = g_offset[gw];
    int end = start + g_count[gw];

    float a00 = 0.f, a01 = 0.f, a10 = 0.f, a11 = 0.f;
    float a20 = 0.f, a21 = 0.f, a30 = 0.f, a31 = 0.f;
    float ws0 = 0.f, ws1 = 0.f, ws2 = 0.f, ws3 = 0.f;
    const half2* xh2 = (const half2*)g_xh;

    for (int base = start; base < end; base += 32) {
        int i = base + lane;
        float w0 = 0.f, w1 = 0.f, w2 = 0.f, w3 = 0.f;
        int src = 0;
        if (i < end) {
            int2 pv = g_pay[i];
            src = pv.x;
            float eav = __int_as_float(pv.y);
            float4 as = *(const float4*)&g_asrc[src * 4];
            float l0 = as.x + adv.x + eav * sh0; l0 = (l0 > 0.f) ? l0 : 0.2f * l0;
            float l1 = as.y + adv.y + eav * sh1; l1 = (l1 > 0.f) ? l1 : 0.2f * l1;
            float l2 = as.z + adv.z + eav * sh2; l2 = (l2 > 0.f) ? l2 : 0.2f * l2;
            float l3 = as.w + adv.w + eav * sh3; l3 = (l3 > 0.f) ? l3 : 0.2f * l3;
            w0 = __expf(l0); w1 = __expf(l1); w2 = __expf(l2); w3 = __expf(l3);
        }
        int cnt = min(32, end - base);
        for (int j = 0; j < cnt; j++) {
            int   s  = __shfl_sync(0xffffffffu, src, j);
            float wa = __shfl_sync(0xffffffffu, w0,  j);
            float wb = __shfl_sync(0xffffffffu, w1,  j);
            float wc = __shfl_sync(0xffffffffu, w2,  j);
            float wd = __shfl_sync(0xffffffffu, w3,  j);
            float2 f = __half22float2(xh2[(size_t)s * 32 + lane]);
            a00 += wa * f.x; a01 += wa * f.y; ws0 += wa;
            a10 += wb * f.x; a11 += wb * f.y; ws1 += wb;
            a20 += wc * f.x; a21 += wc * f.y; ws2 += wc;
            a30 += wd * f.x; a31 += wd * f.y; ws3 += wd;
        }
    }

    float i0 = 0.25f / (ws0 + 1e-16f);   // fold 1/4 head-mean into normalize
    float i1 = 0.25f / (ws1 + 1e-16f);
    float i2 = 0.25f / (ws2 + 1e-16f);
    float i3 = 0.25f / (ws3 + 1e-16f);

    half2* A2 = (half2*)g_A + (size_t)gw * 128 + lane;
    A2[0]  = __floats2half2_rn(a00 * i0, a01 * i0);
    A2[32] = __floats2half2_rn(a10 * i1, a11 * i1);
    A2[64] = __floats2half2_rn(a20 * i2, a21 * i2);
    A2[96] = __floats2half2_rn(a30 * i3, a31 * i3);
}

__device__ __forceinline__ void mma16816(float* c, uint32_t a0, uint32_t a1,
                                         uint32_t a2, uint32_t a3,
                                         uint32_t b0, uint32_t b1) {
    asm("mma.sync.aligned.m16n8k16.row.col.f32.f16.f16.f32 "
        "{%0,%1,%2,%3}, {%4,%5,%6,%7}, {%8,%9}, {%0,%1,%2,%3};"
        : "+f"(c[0]), "+f"(c[1]), "+f"(c[2]), "+f"(c[3])
        : "r"(a0), "r"(a1), "r"(a2), "r"(a3), "r"(b0), "r"(b1));
}

// out = relu( A @ bmat + bias ) + x.
__global__ void k_outgemm(const float* __restrict__ x, const float* __restrict__ bias,
                          float* __restrict__ out, int n) {
    __shared__ __half As[64 * 136];
    __shared__ __half Bs[64 * 136];
    int tid = threadIdx.x;
    int base = blockIdx.x * 64;
    int w = tid >> 5, lane = tid & 31;
    int gid = lane >> 2, tig = lane & 3;
    int r0 = (w & 3) * 16, c0 = (w >> 2) * 32;

    float acc[4][4];
    #pragma unroll
    for (int nt = 0; nt < 4; nt++)
        #pragma unroll
        for (int j = 0; j < 4; j++) acc[nt][j] = 0.0f;

    #pragma unroll
    for (int kh = 0; kh < 2; kh++) {
        for (int i = tid; i < 1024; i += 256) {
            int r = i >> 4, cc = i & 15;
            int node = base + r;
            uint4 v = (node < n) ? *(const uint4*)&g_A[(size_t)node * 256 + kh * 128 + cc * 8]
                                 : make_uint4(0u, 0u, 0u, 0u);
            *(uint4*)&As[r * 136 + cc * 8] = v;
        }
        for (int i = tid; i < 1024; i += 256) {
            int j = i >> 4, cc = i & 15;
            *(uint4*)&Bs[j * 136 + cc * 8] = *(const uint4*)&g_bmat[j * 256 + kh * 128 + cc * 8];
        }
        __syncthreads();
        #pragma unroll
        for (int ks = 0; ks < 8; ks++) {
            const __half* ap = &As[(r0 + gid) * 136 + ks * 16 + 2 * tig];
            uint32_t a0 = *(const uint32_t*)ap;
            uint32_t a1 = *(const uint32_t*)(ap + 8 * 136);
            uint32_t a2 = *(const uint32_t*)(ap + 8);
            uint32_t a3 = *(const uint32_t*)(ap + 8 * 136 + 8);
            #pragma unroll
            for (int nt = 0; nt < 4; nt++) {
                const __half* bp = &Bs[(c0 + nt * 8 + gid) * 136 + ks * 16 + 2 * tig];
                uint32_t b0 = *(const uint32_t*)bp;
                uint32_t b1 = *(const uint32_t*)(bp + 8);
                mma16816(acc[nt], a0, a1, a2, a3, b0, b1);
            }
        }
        __syncthreads();
    }

    int node0 = base + r0 + gid, node1 = node0 + 8;
    #pragma unroll
    for (int nt = 0; nt < 4; nt++) {
        int col = c0 + nt * 8 + 2 * tig;
        float b0v = bias[col], b1v = bias[col + 1];
        if (node0 < n) {
            float2 xv = *(const float2*)&x[(size_t)node0 * 64 + col];
            float2 o;
            o.x = fmaxf(acc[nt][0] + b0v, 0.f) + xv.x;
            o.y = fmaxf(acc[nt][1] + b1v, 0.f) + xv.y;
            *(float2*)&out[(size_t)node0 * 64 + col] = o;
        }
        if (node1 < n) {
            float2 xv = *(const float2*)&x[(size_t)node1 * 64 + col];
            float2 o;
            o.x = fmaxf(acc[nt][2] + b0v, 0.f) + xv.x;
            o.y = fmaxf(acc[nt][3] + b1v, 0.f) + xv.y;
            *(float2*)&out[(size_t)node1 * 64 + col] = o;
        }
    }
}

// ---------------- launcher ----------------
extern "C" void kernel_launch(void* const* d_in, const int* in_sizes, int n_in,
                              void* d_out, int out_size) {
    const float* x        = (const float*)d_in[0];
    const int*   eidx     = (const int*)  d_in[1];
    const float* eattr    = (const float*)d_in[2];
    const float* W        = (const float*)d_in[3];
    const float* att_src  = (const float*)d_in[4];
    const float* att_dst  = (const float*)d_in[5];
    const float* lew      = (const float*)d_in[6];
    const float* att_edge = (const float*)d_in[7];
    const float* bias     = (const float*)d_in[8];
    float* out = (float*)d_out;

    int n = in_sizes[0] / 64;
    int E = in_sizes[2];
    const int* srcidx = eidx;
    const int* dstidx = eidx + E;
    int nb = (n + SCAN_B - 1) / SCAN_B;

    k_prep   <<<512, 256>>>(x, eattr, W, att_src, att_dst, lew, att_edge, n, E);
    k_nc     <<<(E + 255) / 256, 256>>>(dstidx, n, E);
    k_scan   <<<nb, SCAN_B>>>(n, nb, E);
    k_scatter<<<(E + n + 255) / 256, 256>>>(srcidx, dstidx, eattr, E, n);
    k_agg    <<<(n + 7) / 8, 256>>>(n, E);
    k_outgemm<<<(n + 63) / 64, 256>>>(x, bias, out, n);
}